// round 1
// baseline (speedup 1.0000x reference)
#include <cuda_runtime.h>

// Problem constants (fixed by the reference)
#define NN 50000
#define EE 800000
#define CC 64
#define BN_EPS 1e-5f

// ---------------- scratch (static device arrays; no allocation) -------------
__device__ float    g_c1[NN];        // sum_e s_e        per src node
__device__ float    g_c2[NN];        // sum_e s_e^2      per src node
__device__ float    g_S1[CC];        // sum_n c1[n]*Y[n,c]
__device__ float    g_S2[CC];        // sum_n c2[n]*Y[n,c]^2
__device__ float    g_alpha[CC];     // pool-BN scale per channel
__device__ float    g_delta[CC];     // pool-BN shift per channel
__device__ float    g_hsum[CC];      // final-BN sums
__device__ float    g_hsq[CC];
__device__ float    g_a2[CC];
__device__ float    g_b2[CC];
__device__ float    g_Y[NN * CC];    // X @ pool_W
__device__ unsigned g_agg[NN * CC];  // scatter-max result (float bits, >= 0)
__device__ float    g_h[NN * CC];    // pre-BN final features

// ---------------- K0: zero everything the graph replay needs ----------------
__global__ void k0_zero() {
    int i = blockIdx.x * blockDim.x + threadIdx.x;
    int stride = gridDim.x * blockDim.x;
    for (int idx = i; idx < NN * CC; idx += stride) g_agg[idx] = 0u;
    for (int idx = i; idx < NN; idx += stride) { g_c1[idx] = 0.f; g_c2[idx] = 0.f; }
    if (i < CC) { g_S1[i] = 0.f; g_S2[i] = 0.f; g_hsum[i] = 0.f; g_hsq[i] = 0.f; }
}

// ---------------- K1: per-src-node sums of s and s^2 ------------------------
__global__ void k1_edge_stats(const int* __restrict__ ei,
                              const float* __restrict__ ew,
                              const float* __restrict__ coefp) {
    int e = blockIdx.x * blockDim.x + threadIdx.x;
    if (e >= EE) return;
    float coef = __ldg(coefp);
    int src = ei[e];
    float s = fmaf(coef, ew[e], 1.0f);
    atomicAdd(&g_c1[src], s);
    atomicAdd(&g_c2[src], s * s);
}

// ---------------- K2: Y = X @ pool_W  (thread-per-row, W in smem) -----------
__global__ void __launch_bounds__(128) k2_xw(const float* __restrict__ x,
                                             const float* __restrict__ W) {
    __shared__ float Ws[CC * CC];
    for (int i = threadIdx.x; i < CC * CC; i += blockDim.x) Ws[i] = W[i];
    __syncthreads();
    int r = blockIdx.x * blockDim.x + threadIdx.x;
    if (r >= NN) return;
    float y[CC];
#pragma unroll
    for (int c = 0; c < CC; c++) y[c] = 0.f;
    const float4* xr = reinterpret_cast<const float4*>(x + (size_t)r * CC);
#pragma unroll
    for (int k4 = 0; k4 < 16; k4++) {
        float4 xv = xr[k4];
        const float* w0 = &Ws[(k4 * 4 + 0) * CC];
        const float* w1 = &Ws[(k4 * 4 + 1) * CC];
        const float* w2 = &Ws[(k4 * 4 + 2) * CC];
        const float* w3 = &Ws[(k4 * 4 + 3) * CC];
#pragma unroll
        for (int c = 0; c < CC; c += 4) {
            float4 a = *reinterpret_cast<const float4*>(w0 + c);
            float4 b = *reinterpret_cast<const float4*>(w1 + c);
            float4 d = *reinterpret_cast<const float4*>(w2 + c);
            float4 f = *reinterpret_cast<const float4*>(w3 + c);
            y[c + 0] += xv.x * a.x + xv.y * b.x + xv.z * d.x + xv.w * f.x;
            y[c + 1] += xv.x * a.y + xv.y * b.y + xv.z * d.y + xv.w * f.y;
            y[c + 2] += xv.x * a.z + xv.y * b.z + xv.z * d.z + xv.w * f.z;
            y[c + 3] += xv.x * a.w + xv.y * b.w + xv.z * d.w + xv.w * f.w;
        }
    }
    float4* yr = reinterpret_cast<float4*>(g_Y + (size_t)r * CC);
#pragma unroll
    for (int c4 = 0; c4 < 16; c4++) {
        float4 v;
        v.x = y[c4 * 4 + 0]; v.y = y[c4 * 4 + 1];
        v.z = y[c4 * 4 + 2]; v.w = y[c4 * 4 + 3];
        yr[c4] = v;
    }
}

// ---------------- K2b: S1_c = sum c1*Y, S2_c = sum c2*Y^2 -------------------
__global__ void k2b_reduce_Y() {
    int c = threadIdx.x & 63;
    int j = threadIdx.x >> 6;                 // 0..7 (blockDim = 512)
    float a1 = 0.f, a2 = 0.f;
    for (int r = blockIdx.x * 8 + j; r < NN; r += gridDim.x * 8) {
        float v = g_Y[(size_t)r * CC + c];
        a1 += g_c1[r] * v;
        a2 += g_c2[r] * v * v;
    }
    __shared__ float s1[512], s2[512];
    s1[threadIdx.x] = a1; s2[threadIdx.x] = a2;
    __syncthreads();
    if (j == 0) {
#pragma unroll
        for (int jj = 1; jj < 8; jj++) { a1 += s1[jj * 64 + c]; a2 += s2[jj * 64 + c]; }
        atomicAdd(&g_S1[c], a1);
        atomicAdd(&g_S2[c], a2);
    }
}

// ---------------- K3: pool-BN coefficients (1 block, 64 thr) ----------------
__global__ void k3_pool_coeffs(const float* __restrict__ pb,
                               const float* __restrict__ gamma,
                               const float* __restrict__ beta) {
    int c = threadIdx.x;
    float invE = 1.0f / (float)EE;
    float b = pb[c];
    float mean = g_S1[c] * invE + b;
    float msq = (g_S2[c] + 2.f * b * g_S1[c]) * invE + b * b;
    float var = msq - mean * mean;
    float alpha = gamma[c] * rsqrtf(var + BN_EPS);
    g_alpha[c] = alpha;
    g_delta[c] = beta[c] + alpha * (b - mean);
}

// ---------------- K4: per-edge scatter-max (the heavy pass) -----------------
__global__ void k4_scatter(const int* __restrict__ ei,
                           const float* __restrict__ ew,
                           const float* __restrict__ coefp) {
    float coef = __ldg(coefp);
    int lane = threadIdx.x & 31;
    int warp = (blockIdx.x * blockDim.x + threadIdx.x) >> 5;
    int nwarps = (gridDim.x * blockDim.x) >> 5;
    float al0 = g_alpha[2 * lane],     al1 = g_alpha[2 * lane + 1];
    float de0 = g_delta[2 * lane],     de1 = g_delta[2 * lane + 1];
    for (int base = warp * 32; base < EE; base += nwarps * 32) {
        int e = base + lane;
        int src = 0, dst = 0; float s = 0.f;
        if (e < EE) {
            src = ei[e];
            dst = ei[EE + e];
            s = fmaf(coef, ew[e], 1.0f);
        }
        int cnt = min(32, EE - base);
        for (int i = 0; i < cnt; i++) {
            int   sI = __shfl_sync(0xffffffffu, src, i);
            int   dI = __shfl_sync(0xffffffffu, dst, i);
            float sS = __shfl_sync(0xffffffffu, s, i);
            float2 yv = *reinterpret_cast<const float2*>(g_Y + (size_t)sI * CC + 2 * lane);
            float v0 = fmaf(al0 * sS, yv.x, de0);
            float v1 = fmaf(al1 * sS, yv.y, de1);
            unsigned* arow = &g_agg[(size_t)dI * CC + 2 * lane];
            if (v0 > 0.f) atomicMax(arow,     __float_as_uint(v0));
            if (v1 > 0.f) atomicMax(arow + 1, __float_as_uint(v1));
        }
    }
}

// ---------------- K5: h = [x, agg] @ final_W + final_b ----------------------
__global__ void __launch_bounds__(128) k5_final(const float* __restrict__ x,
                                                const float* __restrict__ Wf,
                                                const float* __restrict__ fb) {
    __shared__ float Ws[128 * CC];   // 32 KB
    for (int i = threadIdx.x; i < 128 * CC; i += blockDim.x) Ws[i] = Wf[i];
    __syncthreads();
    int r = blockIdx.x * blockDim.x + threadIdx.x;
    if (r >= NN) return;
    float h[CC];
#pragma unroll
    for (int c = 0; c < CC; c++) h[c] = __ldg(fb + c);

    const float4* xr = reinterpret_cast<const float4*>(x + (size_t)r * CC);
    const float4* ar = reinterpret_cast<const float4*>(&g_agg[(size_t)r * CC]);
#pragma unroll
    for (int half = 0; half < 2; half++) {
        const float4* src4 = (half == 0) ? xr : ar;
        const float* Wbase = &Ws[half * 64 * CC];
#pragma unroll
        for (int k4 = 0; k4 < 16; k4++) {
            float4 xv = src4[k4];
            const float* w0 = Wbase + (k4 * 4 + 0) * CC;
            const float* w1 = Wbase + (k4 * 4 + 1) * CC;
            const float* w2 = Wbase + (k4 * 4 + 2) * CC;
            const float* w3 = Wbase + (k4 * 4 + 3) * CC;
#pragma unroll
            for (int c = 0; c < CC; c += 4) {
                float4 a = *reinterpret_cast<const float4*>(w0 + c);
                float4 b = *reinterpret_cast<const float4*>(w1 + c);
                float4 d = *reinterpret_cast<const float4*>(w2 + c);
                float4 f = *reinterpret_cast<const float4*>(w3 + c);
                h[c + 0] += xv.x * a.x + xv.y * b.x + xv.z * d.x + xv.w * f.x;
                h[c + 1] += xv.x * a.y + xv.y * b.y + xv.z * d.y + xv.w * f.y;
                h[c + 2] += xv.x * a.z + xv.y * b.z + xv.z * d.z + xv.w * f.z;
                h[c + 3] += xv.x * a.w + xv.y * b.w + xv.z * d.w + xv.w * f.w;
            }
        }
    }
    float4* hr = reinterpret_cast<float4*>(g_h + (size_t)r * CC);
#pragma unroll
    for (int c4 = 0; c4 < 16; c4++) {
        float4 v;
        v.x = h[c4 * 4 + 0]; v.y = h[c4 * 4 + 1];
        v.z = h[c4 * 4 + 2]; v.w = h[c4 * 4 + 3];
        hr[c4] = v;
    }
}

// ---------------- K5b: per-channel sum/sumsq of h ---------------------------
__global__ void k5b_reduce_h() {
    int c = threadIdx.x & 63;
    int j = threadIdx.x >> 6;
    float a1 = 0.f, a2 = 0.f;
    for (int r = blockIdx.x * 8 + j; r < NN; r += gridDim.x * 8) {
        float v = g_h[(size_t)r * CC + c];
        a1 += v;
        a2 += v * v;
    }
    __shared__ float s1[512], s2[512];
    s1[threadIdx.x] = a1; s2[threadIdx.x] = a2;
    __syncthreads();
    if (j == 0) {
#pragma unroll
        for (int jj = 1; jj < 8; jj++) { a1 += s1[jj * 64 + c]; a2 += s2[jj * 64 + c]; }
        atomicAdd(&g_hsum[c], a1);
        atomicAdd(&g_hsq[c], a2);
    }
}

// ---------------- K6: final-BN coefficients ---------------------------------
__global__ void k6_final_coeffs(const float* __restrict__ gamma,
                                const float* __restrict__ beta) {
    int c = threadIdx.x;
    float invN = 1.0f / (float)NN;
    float mean = g_hsum[c] * invN;
    float var = g_hsq[c] * invN - mean * mean;
    float a = gamma[c] * rsqrtf(var + BN_EPS);
    g_a2[c] = a;
    g_b2[c] = beta[c] - a * mean;
}

// ---------------- K7: out = relu(a2*h + b2) ---------------------------------
__global__ void k7_epilogue(float* __restrict__ out) {
    int i = blockIdx.x * blockDim.x + threadIdx.x;
    int stride = gridDim.x * blockDim.x;
    const float4* hv = reinterpret_cast<const float4*>(g_h);
    float4* ov = reinterpret_cast<float4*>(out);
    for (int q = i; q < NN * 16; q += stride) {
        int c4 = (q & 15) * 4;
        float4 h = hv[q];
        float4 r;
        r.x = fmaxf(0.f, fmaf(g_a2[c4 + 0], h.x, g_b2[c4 + 0]));
        r.y = fmaxf(0.f, fmaf(g_a2[c4 + 1], h.y, g_b2[c4 + 1]));
        r.z = fmaxf(0.f, fmaf(g_a2[c4 + 2], h.z, g_b2[c4 + 2]));
        r.w = fmaxf(0.f, fmaf(g_a2[c4 + 3], h.w, g_b2[c4 + 3]));
        ov[q] = r;
    }
}

// ---------------- launch -----------------------------------------------------
extern "C" void kernel_launch(void* const* d_in, const int* in_sizes, int n_in,
                              void* d_out, int out_size) {
    const float* x     = (const float*)d_in[0];
    const int*   ei    = (const int*)d_in[1];
    const float* ew    = (const float*)d_in[2];
    const float* pW    = (const float*)d_in[3];
    const float* pb    = (const float*)d_in[4];
    const float* pg    = (const float*)d_in[5];
    const float* pbeta = (const float*)d_in[6];
    const float* fW    = (const float*)d_in[7];
    const float* fb    = (const float*)d_in[8];
    const float* fg    = (const float*)d_in[9];
    const float* fbeta = (const float*)d_in[10];
    const float* coef  = (const float*)d_in[11];
    float* out = (float*)d_out;

    k0_zero<<<2048, 256>>>();
    k1_edge_stats<<<(EE + 255) / 256, 256>>>(ei, ew, coef);
    k2_xw<<<(NN + 127) / 128, 128>>>(x, pW);
    k2b_reduce_Y<<<128, 512>>>();
    k3_pool_coeffs<<<1, 64>>>(pb, pg, pbeta);
    k4_scatter<<<592, 256>>>(ei, ew, coef);
    k5_final<<<(NN + 127) / 128, 128>>>(x, fW, fb);
    k5b_reduce_h<<<128, 512>>>();
    k6_final_coeffs<<<1, 64>>>(fg, fbeta);
    k7_epilogue<<<1024, 256>>>(out);
}